// round 16
// baseline (speedup 1.0000x reference)
#include <cuda_runtime.h>
#include <cuda_fp16.h>
#include <math.h>

// ESN: B=256, T=512, D=64, N=512, leak=0.5
// Output: [ X (B,T,N) fp32 ][ X_last (B,N) fp32 ]

#define BB 256
#define TT 512
#define DD 64
#define NN 512
#define LEAK 0.5f
#define NCTA 256       // 8 m-slabs x 32 n-tiles(16 wide); 2 CTAs/SM
#define ASH 520        // Asm row stride in halves
#define WBS32 528      // Wb entry stride in words
#define NGRP 8
#define HALF_SZ 16     // producers per half-counter (n-tiles per 256-col half)

typedef unsigned long long ull;

__device__ unsigned g_cnt[NGRP * 2 * 32];    // 128B-spaced half counters
__device__ __half g_xt[2][BB][NN];           // fp16 x_t, double-buffered

__device__ __forceinline__ void fma2(ull &acc, ull a, ull b) {
    asm("fma.rn.f32x2 %0, %1, %2, %0;" : "+l"(acc) : "l"(a), "l"(b));
}
__device__ __forceinline__ float2 unpack2(ull v) {
    float2 r; asm("mov.b64 {%0, %1}, %2;" : "=f"(r.x), "=f"(r.y) : "l"(v)); return r;
}
__device__ __forceinline__ unsigned atom_add_rel(unsigned* p, unsigned v) {
    unsigned r;
    asm volatile("atom.add.release.gpu.global.u32 %0, [%1], %2;"
                 : "=r"(r) : "l"(p), "r"(v) : "memory");
    return r;
}
__device__ __forceinline__ unsigned ld_acq(const unsigned* p) {
    unsigned r;
    asm volatile("ld.acquire.gpu.global.u32 %0, [%1];" : "=r"(r) : "l"(p) : "memory");
    return r;
}
__device__ __forceinline__ void mma16(float &c0, float &c1, float &c2, float &c3,
                                      unsigned a0, unsigned a1, unsigned a2, unsigned a3,
                                      unsigned b0, unsigned b1) {
    asm("mma.sync.aligned.m16n8k16.row.col.f32.f16.f16.f32 "
        "{%0,%1,%2,%3},{%4,%5,%6,%7},{%8,%9},{%0,%1,%2,%3};"
        : "+f"(c0), "+f"(c1), "+f"(c2), "+f"(c3)
        : "r"(a0), "r"(a1), "r"(a2), "r"(a3), "r"(b0), "r"(b1));
}

// ---------------------------------------------------------------------------
// Projection: U = inputs@W_in + b_in; x0 = leak*tanh(U0) at t=0 (also fp16
// into g_xt[0]). Block (0,0) resets the half counters.
// ---------------------------------------------------------------------------
__global__ __launch_bounds__(128) void proj_kernel(
    const float* __restrict__ inp, const float* __restrict__ Win,
    const float* __restrict__ bin, float* __restrict__ X)
{
    __shared__ __align__(16) float Ash[DD][36];
    __shared__ __align__(16) float Wd[DD][64];

    const int tid = threadIdx.x;
    const int m0 = blockIdx.x * 32;
    const int n0 = blockIdx.y * 32;

    if (blockIdx.x == 0 && blockIdx.y == 0 && tid < NGRP * 2)
        g_cnt[tid * 32] = 0u;

    {
        int c = tid & 63, mi = tid >> 6;
        #pragma unroll
        for (int j = 0; j < 16; j++) {
            int m = j * 2 + mi;
            Ash[c][m] = inp[(m0 + m) * DD + c];
        }
    }
    {
        int n = tid & 31, kw = tid >> 5;
        #pragma unroll
        for (int j = 0; j < 16; j++) {
            int k = j * 4 + kw;
            float w = Win[k * NN + n0 + n];
            Wd[k][2 * n] = w; Wd[k][2 * n + 1] = w;
        }
    }
    __syncthreads();

    const int tx = tid & 7;
    const int ty = tid >> 3;
    ull acc0 = 0, acc1 = 0, acc2 = 0, acc3 = 0;

    #pragma unroll
    for (int k = 0; k < DD; k++) {
        ull a = *(const ull*)&Ash[k][2 * ty];
        const ulonglong2* bp = (const ulonglong2*)&Wd[k][8 * tx];
        ulonglong2 b01 = bp[0], b23 = bp[1];
        fma2(acc0, a, b01.x); fma2(acc1, a, b01.y);
        fma2(acc2, a, b23.x); fma2(acc3, a, b23.y);
    }

    const int r0 = m0 + 2 * ty;
    const int t0 = r0 & (TT - 1);
    const int nb = n0 + 4 * tx;
    ull accs[4] = {acc0, acc1, acc2, acc3};
    #pragma unroll
    for (int c = 0; c < 4; c++) {
        float2 v = unpack2(accs[c]);
        int n = nb + c;
        float b = bin[n];
        float u0 = v.x + b;
        float u1 = v.y + b;
        if (t0 == 0) {
            float x0 = LEAK * tanhf(u0);
            X[(size_t)r0 * NN + n] = x0;
            g_xt[0][r0 >> 9][n] = __float2half_rn(x0);
        } else {
            X[(size_t)r0 * NN + n] = u0;
        }
        X[(size_t)(r0 + 1) * NN + n] = u1;
    }
}

// ---------------------------------------------------------------------------
// Persistent fp16 tensor-core recurrence, 2 CTAs/SM:
// 256 CTAs = 8 m-slabs x 32 n-tiles(16 cols); 128 threads = 4 warps =
// 2 m-halves (wm) x 2 k-halves (kh). kh groups (64 thr) poll/stage/GEMM
// their k-half independently (named barriers); each warp owns the n8-chain
// kh, exchanges the other with warp^2 via Rsm; 4-tanh epilogue on all warps.
// Co-resident CTAs are in different m-groups -> chains overlap on the SM.
// ---------------------------------------------------------------------------
__global__ __launch_bounds__(128, 2) void esn_mma(
    float* __restrict__ X, const float* __restrict__ Wres,
    const float* __restrict__ bres, float* __restrict__ xlast)
{
    extern __shared__ __align__(16) char smem[];
    __half* Asm = (__half*)smem;                     // [32][ASH] halves
    float*  Wb  = (float*)(smem + 32 * ASH * 2);     // [8][WBS32] words
    float*  Rsm = Wb + 8 * WBS32;                    // [4][32][4] exchange

    const int tid  = threadIdx.x;
    const int warp = tid >> 5, lane = tid & 31;
    const int wm   = warp & 1;          // m-half
    const int kh   = warp >> 1;         // k-half / owned n8-chain
    const int gid  = lane >> 2, tig = lane & 3;
    const int bx   = blockIdx.x;
    const int grp  = bx & 7;            // m-slab
    const int nt   = bx >> 3;           // n-tile 0..31 (16 cols)
    const int m0   = grp * 32;
    const int n0   = nt * 16;
    const int TN   = TT * NN;

    unsigned* own   = &g_cnt[(grp * 2 + (nt >> 4)) * 32];
    unsigned* mycnt = &g_cnt[(grp * 2 + kh) * 32];

    // ---- stage quad-packed fp16 W once: 8 entries x 32 k16 x 4 tg ----
    for (int idx = tid; idx < 1024; idx += 128) {
        int e  = idx >> 7;              // 0..7
        int rem = idx & 127;
        int j  = rem >> 2;              // k16 index 0..31
        int tg = rem & 3;
        int k0 = 16 * j + 2 * tg;
        int nA = n0 + e;
        __half2* d = (__half2*)(Wb + e * WBS32 + j * 16 + tg * 4);
        d[0] = __floats2half2_rn(Wres[(size_t)k0 * NN + nA],
                                 Wres[(size_t)(k0 + 1) * NN + nA]);
        d[1] = __floats2half2_rn(Wres[(size_t)(k0 + 8) * NN + nA],
                                 Wres[(size_t)(k0 + 9) * NN + nA]);
        d[2] = __floats2half2_rn(Wres[(size_t)k0 * NN + nA + 8],
                                 Wres[(size_t)(k0 + 1) * NN + nA + 8]);
        d[3] = __floats2half2_rn(Wres[(size_t)(k0 + 8) * NN + nA + 8],
                                 Wres[(size_t)(k0 + 9) * NN + nA + 8]);
    }

    const int r0  = m0 + 16 * wm + gid;         // rows r0, r0+8
    const int myc = n0 + 8 * kh + 2 * tig;      // this warp's owned cols
    const __half* arow0 = Asm + (16 * wm + gid) * ASH + kh * 256;
    const __half* arow1 = arow0 + 8 * ASH;
    const float* wbp = Wb + gid * WBS32 + kh * 256 + tig * 4;
    float* rme   = Rsm + (((warp ^ 2) * 32) + lane) * 4;   // write peer's slot
    const float* rpe = Rsm + ((warp * 32) + lane) * 4;     // read own slot

    // staging mapping within each 64-thread kh-group:
    // rows sr8, sr8+8, sr8+16, sr8+24; 4 f4-cols each (8 thr/row, 128B runs)
    const int idxg = wm * 32 + lane;         // 0..63
    const int sr8 = idxg >> 3;               // 0..7
    const int sg  = idxg & 7;                // f4 phase
    const int colbase = kh * 32;             // f4-col offset of this k-half

    const float2 br = *(const float2*)&bres[myc];

    // register-carried x_prev + U prefetch for t=1 (all warps, own cols)
    float2 p0 = *(const float2*)&X[(size_t)r0 * TN + myc];
    float2 p1 = *(const float2*)&X[(size_t)(r0 + 8) * TN + myc];
    float2 u0, u1;
    {
        size_t b1 = (size_t)r0 * TN + (size_t)1 * NN + myc;
        u0 = __ldcg((const float2*)&X[b1]);
        u1 = __ldcg((const float2*)&X[b1 + (size_t)8 * TN]);
    }
    __syncthreads();   // Wb ready

    for (int t = 1; t < TT; t++) {
        const int par = (t - 1) & 1;

        // ---- split-phase: poll own k-half, stage own k-half (fp16) ----
        if (wm == 0 && lane == 0) {
            unsigned target = (unsigned)(t - 1) * HALF_SZ;
            while (ld_acq(mycnt) < target) { }
        }
        asm volatile("bar.sync %0, 64;" :: "r"(1 + kh) : "memory");

        {
            #pragma unroll
            for (int rr = 0; rr < 4; rr++) {
                int row = sr8 + 8 * rr;
                const float4* rp = (const float4*)&g_xt[par][m0 + row][0];
                __half* dr = Asm + row * ASH;
                #pragma unroll
                for (int j = 0; j < 4; j++) {
                    int i4 = colbase + sg + 8 * j;
                    float4 v = __ldcg(rp + i4);
                    *(float4*)(dr + 8 * i4) = v;
                }
            }
        }
        asm volatile("bar.sync %0, 64;" :: "r"(1 + kh) : "memory");

        // ---- GEMM over this warp's k-half: 16 k16, 2 n8 chains ----
        float h00 = 0.f, h01 = 0.f, h02 = 0.f, h03 = 0.f;   // n8=0
        float h10 = 0.f, h11 = 0.f, h12 = 0.f, h13 = 0.f;   // n8=1
        #pragma unroll 8
        for (int j = 0; j < 16; j++) {
            int kk = 16 * j + 2 * tig;
            unsigned a0 = *(const unsigned*)(arow0 + kk);
            unsigned a1 = *(const unsigned*)(arow1 + kk);
            unsigned a2 = *(const unsigned*)(arow0 + kk + 8);
            unsigned a3 = *(const unsigned*)(arow1 + kk + 8);
            uint4 b = *(const uint4*)(wbp + j * 16);
            mma16(h00, h01, h02, h03, a0, a1, a2, a3, b.x, b.y);
            mma16(h10, h11, h12, h13, a0, a1, a2, a3, b.z, b.w);
        }

        // ---- symmetric exchange with warp^2: ship the chain we don't own ----
        if (kh == 0) *(float4*)rme = make_float4(h10, h11, h12, h13);
        else         *(float4*)rme = make_float4(h00, h01, h02, h03);
        __syncthreads();

        float4 pv = *(const float4*)rpe;
        float s0, s1, s2, s3;
        if (kh == 0) { s0 = h00 + pv.x; s1 = h01 + pv.y; s2 = h02 + pv.z; s3 = h03 + pv.w; }
        else         { s0 = h10 + pv.x; s1 = h11 + pv.y; s2 = h12 + pv.z; s3 = h13 + pv.w; }

        // ---- epilogue on own 4 outputs (all 4 warps) ----
        size_t base = (size_t)r0 * TN + (size_t)t * NN + myc;
        float2 o0, o1;
        o0.x = 0.5f * p0.x + 0.5f * tanhf(u0.x + s0 + br.x);
        o0.y = 0.5f * p0.y + 0.5f * tanhf(u0.y + s1 + br.y);
        o1.x = 0.5f * p1.x + 0.5f * tanhf(u1.x + s2 + br.x);
        o1.y = 0.5f * p1.y + 0.5f * tanhf(u1.y + s3 + br.y);
        p0 = o0; p1 = o1;

        // peers only need g_xt (fp16) -> store it first
        *(__half2*)&g_xt[t & 1][r0][myc]     = __floats2half2_rn(o0.x, o0.y);
        *(__half2*)&g_xt[t & 1][r0 + 8][myc] = __floats2half2_rn(o1.x, o1.y);

        if (t < TT - 1) {
            __syncthreads();                       // g_xt stores done CTA-wide
            if (tid == 0) atom_add_rel(own, 1u);   // release ASAP
            // off-critical-path: X stores + next U prefetch overlap the poll
            *(float2*)&X[base]                  = o0;
            *(float2*)&X[base + (size_t)8 * TN] = o1;
            size_t bn = base + NN;
            u0 = __ldcg((const float2*)&X[bn]);
            u1 = __ldcg((const float2*)&X[bn + (size_t)8 * TN]);
        } else {
            *(float2*)&X[base]                  = o0;
            *(float2*)&X[base + (size_t)8 * TN] = o1;
            *(float2*)&xlast[(size_t)r0 * NN + myc]       = o0;
            *(float2*)&xlast[(size_t)(r0 + 8) * NN + myc] = o1;
        }
    }
}

extern "C" void kernel_launch(void* const* d_in, const int* in_sizes, int n_in,
                              void* d_out, int out_size)
{
    const float* inp  = (const float*)d_in[0];
    const float* Win  = (const float*)d_in[1];
    const float* bin  = (const float*)d_in[2];
    const float* Wres = (const float*)d_in[3];
    const float* bres = (const float*)d_in[4];

    float* X = (float*)d_out;                       // (B, T, N)
    float* xlast = X + (size_t)BB * TT * NN;        // (B, N)

    const int smem_bytes = 32 * ASH * 2 + (8 * WBS32 + 4 * 32 * 4) * 4;  // 52224
    cudaFuncSetAttribute(esn_mma, cudaFuncAttributeMaxDynamicSharedMemorySize, smem_bytes);

    dim3 g1(BB * TT / 32, NN / 32);
    proj_kernel<<<g1, 128>>>(inp, Win, bin, X);

    esn_mma<<<NCTA, 128, smem_bytes>>>(X, Wres, bres, xlast);
}

// round 17
// speedup vs baseline: 1.1189x; 1.1189x over previous
#include <cuda_runtime.h>
#include <cuda_fp16.h>
#include <math.h>

// ESN: B=256, T=512, D=64, N=512, leak=0.5
// Output: [ X (B,T,N) fp32 ][ X_last (B,N) fp32 ]

#define BB 256
#define TT 512
#define DD 64
#define NN 512
#define LEAK 0.5f
#define NCTA 128       // 8 m-slabs x 16 n-tiles(32 wide); 1 CTA/SM
#define ASH 520        // Asm row stride in halves
#define WBS32 528      // Wb entry stride in words
#define NGRP 8
#define HALF_SZ 8      // CTAs per half-counter

typedef unsigned long long ull;

__device__ unsigned g_cnt[NGRP * 2 * 32];    // 128B-spaced half counters
__device__ __half g_xt[2][BB][NN];           // fp16 x_t, double-buffered

__device__ __forceinline__ void fma2(ull &acc, ull a, ull b) {
    asm("fma.rn.f32x2 %0, %1, %2, %0;" : "+l"(acc) : "l"(a), "l"(b));
}
__device__ __forceinline__ float2 unpack2(ull v) {
    float2 r; asm("mov.b64 {%0, %1}, %2;" : "=f"(r.x), "=f"(r.y) : "l"(v)); return r;
}
__device__ __forceinline__ unsigned atom_add_rel(unsigned* p, unsigned v) {
    unsigned r;
    asm volatile("atom.add.release.gpu.global.u32 %0, [%1], %2;"
                 : "=r"(r) : "l"(p), "r"(v) : "memory");
    return r;
}
__device__ __forceinline__ unsigned ld_acq(const unsigned* p) {
    unsigned r;
    asm volatile("ld.acquire.gpu.global.u32 %0, [%1];" : "=r"(r) : "l"(p) : "memory");
    return r;
}
__device__ __forceinline__ float tanh_fast(float x) {
    float r; asm("tanh.approx.f32 %0, %1;" : "=f"(r) : "f"(x));
    return r;
}
__device__ __forceinline__ void mma16(float &c0, float &c1, float &c2, float &c3,
                                      unsigned a0, unsigned a1, unsigned a2, unsigned a3,
                                      unsigned b0, unsigned b1) {
    asm("mma.sync.aligned.m16n8k16.row.col.f32.f16.f16.f32 "
        "{%0,%1,%2,%3},{%4,%5,%6,%7},{%8,%9},{%0,%1,%2,%3};"
        : "+f"(c0), "+f"(c1), "+f"(c2), "+f"(c3)
        : "r"(a0), "r"(a1), "r"(a2), "r"(a3), "r"(b0), "r"(b1));
}

// ---------------------------------------------------------------------------
// Projection: U = inputs@W_in + b_in; x0 = leak*tanh(U0) at t=0 (also fp16
// into g_xt[0]). Block (0,0) resets the half counters.
// ---------------------------------------------------------------------------
__global__ __launch_bounds__(128) void proj_kernel(
    const float* __restrict__ inp, const float* __restrict__ Win,
    const float* __restrict__ bin, float* __restrict__ X)
{
    __shared__ __align__(16) float Ash[DD][36];
    __shared__ __align__(16) float Wd[DD][64];

    const int tid = threadIdx.x;
    const int m0 = blockIdx.x * 32;
    const int n0 = blockIdx.y * 32;

    if (blockIdx.x == 0 && blockIdx.y == 0 && tid < NGRP * 2)
        g_cnt[tid * 32] = 0u;

    {
        int c = tid & 63, mi = tid >> 6;
        #pragma unroll
        for (int j = 0; j < 16; j++) {
            int m = j * 2 + mi;
            Ash[c][m] = inp[(m0 + m) * DD + c];
        }
    }
    {
        int n = tid & 31, kw = tid >> 5;
        #pragma unroll
        for (int j = 0; j < 16; j++) {
            int k = j * 4 + kw;
            float w = Win[k * NN + n0 + n];
            Wd[k][2 * n] = w; Wd[k][2 * n + 1] = w;
        }
    }
    __syncthreads();

    const int tx = tid & 7;
    const int ty = tid >> 3;
    ull acc0 = 0, acc1 = 0, acc2 = 0, acc3 = 0;

    #pragma unroll
    for (int k = 0; k < DD; k++) {
        ull a = *(const ull*)&Ash[k][2 * ty];
        const ulonglong2* bp = (const ulonglong2*)&Wd[k][8 * tx];
        ulonglong2 b01 = bp[0], b23 = bp[1];
        fma2(acc0, a, b01.x); fma2(acc1, a, b01.y);
        fma2(acc2, a, b23.x); fma2(acc3, a, b23.y);
    }

    const int r0 = m0 + 2 * ty;
    const int t0 = r0 & (TT - 1);
    const int nb = n0 + 4 * tx;
    ull accs[4] = {acc0, acc1, acc2, acc3};
    #pragma unroll
    for (int c = 0; c < 4; c++) {
        float2 v = unpack2(accs[c]);
        int n = nb + c;
        float b = bin[n];
        float u0 = v.x + b;
        float u1 = v.y + b;
        if (t0 == 0) {
            float x0 = LEAK * tanhf(u0);
            X[(size_t)r0 * NN + n] = x0;
            g_xt[0][r0 >> 9][n] = __float2half_rn(x0);
        } else {
            X[(size_t)r0 * NN + n] = u0;
        }
        X[(size_t)(r0 + 1) * NN + n] = u1;
    }
}

// ---------------------------------------------------------------------------
// Persistent fp16 tensor-core recurrence, SYMMETRIC epilogue (R14 skeleton):
// 128 CTAs = 8 m-slabs x 16 n-tiles(32); 8 warps = wm x wn x kh.
// kh groups poll/stage/GEMM their k-half independently; each warp keeps the
// n8-half it owns (kh==n8), exchanges the other via Rsm with warp^4, then
// runs a 4-tanh.approx epilogue on its own 4 outputs.
// ---------------------------------------------------------------------------
__global__ __launch_bounds__(256, 1) void esn_mma(
    float* __restrict__ X, const float* __restrict__ Wres,
    const float* __restrict__ bres, float* __restrict__ xlast)
{
    extern __shared__ __align__(16) char smem[];
    __half* Asm = (__half*)smem;                     // [32][ASH] halves
    float*  Wb  = (float*)(smem + 32 * ASH * 2);     // [16][WBS32] words
    float*  Rsm = Wb + 16 * WBS32;                   // [8][32][4] exchange

    const int tid  = threadIdx.x;
    const int warp = tid >> 5, lane = tid & 31;
    const int wm   = warp & 1;
    const int wn   = (warp >> 1) & 1;
    const int kh   = warp >> 2;         // k-half / owned n8-half
    const int gid  = lane >> 2, tig = lane & 3;
    const int bx   = blockIdx.x;
    const int grp  = bx & 7;
    const int nt   = bx >> 3;
    const int m0   = grp * 32;
    const int n0   = nt * 32;
    const int TN   = TT * NN;

    unsigned* own   = &g_cnt[(grp * 2 + (nt >> 3)) * 32];
    unsigned* mycnt = &g_cnt[(grp * 2 + kh) * 32];

    // ---- stage quad-packed fp16 W once ----
    for (int idx = tid; idx < 2048; idx += 256) {
        int e  = idx >> 7;
        int rem = idx & 127;
        int j  = rem >> 2;
        int tg = rem & 3;
        int k0 = 16 * j + 2 * tg;
        int nA = n0 + (e >> 3) * 16 + (e & 7);
        __half2* d = (__half2*)(Wb + e * WBS32 + j * 16 + tg * 4);
        d[0] = __floats2half2_rn(Wres[(size_t)k0 * NN + nA],
                                 Wres[(size_t)(k0 + 1) * NN + nA]);
        d[1] = __floats2half2_rn(Wres[(size_t)(k0 + 8) * NN + nA],
                                 Wres[(size_t)(k0 + 9) * NN + nA]);
        d[2] = __floats2half2_rn(Wres[(size_t)k0 * NN + nA + 8],
                                 Wres[(size_t)(k0 + 1) * NN + nA + 8]);
        d[3] = __floats2half2_rn(Wres[(size_t)(k0 + 8) * NN + nA + 8],
                                 Wres[(size_t)(k0 + 9) * NN + nA + 8]);
    }

    const int r0  = m0 + 16 * wm + gid;         // rows r0, r0+8
    const int cb  = n0 + 16 * wn + 2 * tig;     // n8=0 col base
    const int myc = cb + 8 * kh;                // this warp's owned cols
    const __half* arow0 = Asm + (16 * wm + gid) * ASH + kh * 256;
    const __half* arow1 = arow0 + 8 * ASH;
    const float* wbp = Wb + (wn * 8 + gid) * WBS32 + kh * 256 + tig * 4;
    float* rme   = Rsm + (warp * 32 + lane) * 4;
    const float* rpe = Rsm + ((warp ^ 4) * 32 + lane) * 4;

    // staging mapping within each 128-thread group
    const int wprime = warp & 3;
    const int idxg = wprime * 32 + lane;
    const int sr = idxg >> 3;
    const int sg = idxg & 7;
    const int colbase = kh * 32;

    const float2 br = *(const float2*)&bres[myc];

    // register-carried x_prev + U prefetch for t=1 (all warps, own cols)
    float2 p0 = *(const float2*)&X[(size_t)r0 * TN + myc];
    float2 p1 = *(const float2*)&X[(size_t)(r0 + 8) * TN + myc];
    float2 u0, u1;
    {
        size_t b1 = (size_t)r0 * TN + (size_t)1 * NN + myc;
        u0 = __ldcg((const float2*)&X[b1]);
        u1 = __ldcg((const float2*)&X[b1 + (size_t)8 * TN]);
    }
    __syncthreads();   // Wb ready

    for (int t = 1; t < TT; t++) {
        const int par = (t - 1) & 1;

        // ---- split-phase: poll own k-half, stage own k-half (fp16) ----
        if (wprime == 0 && lane == 0) {
            unsigned target = (unsigned)(t - 1) * HALF_SZ;
            while (ld_acq(mycnt) < target) { }
        }
        asm volatile("bar.sync %0, 128;" :: "r"(1 + kh) : "memory");

        {
            const float4* rp0 = (const float4*)&g_xt[par][m0 + sr][0];
            const float4* rp1 = (const float4*)&g_xt[par][m0 + sr + 16][0];
            __half* dr0 = Asm + sr * ASH;
            __half* dr1 = Asm + (sr + 16) * ASH;
            #pragma unroll
            for (int j = 0; j < 4; j++) {
                int i4 = colbase + sg + 8 * j;
                float4 v0 = __ldcg(rp0 + i4);
                float4 v1 = __ldcg(rp1 + i4);
                *(float4*)(dr0 + 8 * i4) = v0;
                *(float4*)(dr1 + 8 * i4) = v1;
            }
        }
        asm volatile("bar.sync %0, 128;" :: "r"(1 + kh) : "memory");

        // ---- GEMM over this warp's k-half ----
        float h00 = 0.f, h01 = 0.f, h02 = 0.f, h03 = 0.f;   // n8=0
        float h10 = 0.f, h11 = 0.f, h12 = 0.f, h13 = 0.f;   // n8=1
        #pragma unroll 8
        for (int j = 0; j < 16; j++) {
            int kk = 16 * j + 2 * tig;
            unsigned a0 = *(const unsigned*)(arow0 + kk);
            unsigned a1 = *(const unsigned*)(arow1 + kk);
            unsigned a2 = *(const unsigned*)(arow0 + kk + 8);
            unsigned a3 = *(const unsigned*)(arow1 + kk + 8);
            uint4 b = *(const uint4*)(wbp + j * 16);
            mma16(h00, h01, h02, h03, a0, a1, a2, a3, b.x, b.y);
            mma16(h10, h11, h12, h13, a0, a1, a2, a3, b.z, b.w);
        }

        // ---- symmetric exchange: write the half we do NOT own ----
        if (kh == 0) *(float4*)rme = make_float4(h10, h11, h12, h13);
        else         *(float4*)rme = make_float4(h00, h01, h02, h03);
        __syncthreads();

        float4 pv = *(const float4*)rpe;
        float s0, s1, s2, s3;
        if (kh == 0) { s0 = h00 + pv.x; s1 = h01 + pv.y; s2 = h02 + pv.z; s3 = h03 + pv.w; }
        else         { s0 = h10 + pv.x; s1 = h11 + pv.y; s2 = h12 + pv.z; s3 = h13 + pv.w; }

        // ---- epilogue on own 4 outputs (all 8 warps), HW tanh ----
        size_t base = (size_t)r0 * TN + (size_t)t * NN + myc;
        float2 o0, o1;
        o0.x = 0.5f * p0.x + 0.5f * tanh_fast(u0.x + s0 + br.x);
        o0.y = 0.5f * p0.y + 0.5f * tanh_fast(u0.y + s1 + br.y);
        o1.x = 0.5f * p1.x + 0.5f * tanh_fast(u1.x + s2 + br.x);
        o1.y = 0.5f * p1.y + 0.5f * tanh_fast(u1.y + s3 + br.y);
        p0 = o0; p1 = o1;

        // peers only need g_xt (fp16) -> store it first
        *(__half2*)&g_xt[t & 1][r0][myc]     = __floats2half2_rn(o0.x, o0.y);
        *(__half2*)&g_xt[t & 1][r0 + 8][myc] = __floats2half2_rn(o1.x, o1.y);

        if (t < TT - 1) {
            __syncthreads();                       // g_xt stores done CTA-wide
            if (tid == 0) atom_add_rel(own, 1u);   // release ASAP
            // off-critical-path: X stores + next U prefetch overlap the poll
            *(float2*)&X[base]                  = o0;
            *(float2*)&X[base + (size_t)8 * TN] = o1;
            size_t bn = base + NN;
            u0 = __ldcg((const float2*)&X[bn]);
            u1 = __ldcg((const float2*)&X[bn + (size_t)8 * TN]);
        } else {
            *(float2*)&X[base]                  = o0;
            *(float2*)&X[base + (size_t)8 * TN] = o1;
            *(float2*)&xlast[(size_t)r0 * NN + myc]       = o0;
            *(float2*)&xlast[(size_t)(r0 + 8) * NN + myc] = o1;
        }
    }
}

extern "C" void kernel_launch(void* const* d_in, const int* in_sizes, int n_in,
                              void* d_out, int out_size)
{
    const float* inp  = (const float*)d_in[0];
    const float* Win  = (const float*)d_in[1];
    const float* bin  = (const float*)d_in[2];
    const float* Wres = (const float*)d_in[3];
    const float* bres = (const float*)d_in[4];

    float* X = (float*)d_out;                       // (B, T, N)
    float* xlast = X + (size_t)BB * TT * NN;        // (B, N)

    const int smem_bytes = 32 * ASH * 2 + (16 * WBS32 + 8 * 32 * 4) * 4;  // 71168
    cudaFuncSetAttribute(esn_mma, cudaFuncAttributeMaxDynamicSharedMemorySize, smem_bytes);

    dim3 g1(BB * TT / 32, NN / 32);
    proj_kernel<<<g1, 128>>>(inp, Win, bin, X);

    esn_mma<<<NCTA, 256, smem_bytes>>>(X, Wres, bres, xlast);
}